// round 14
// baseline (speedup 1.0000x reference)
#include <cuda_runtime.h>
#include <math.h>
#include <stdint.h>

// Problem constants
#define NA 16
#define NS 64
#define NB 100
#define NE 12
#define MAXLEN 20
#define DD 512
#define NCOL (NA*NE)          // 192
#define NGRP (NA*NS)          // 1024
#define NROW (NGRP*NB)        // 102400
#define EPSF 1e-5f
#define DELTA_F 0.2f

// Output layout (float32, concatenated flattened in return order)
#define OUT_DIND 0
#define OUT_DSIM (NGRP*NCOL)            // 196608
#define OUT_MARGIN (2*NGRP*NCOL)        // 393216
#define OUT_DTI (2*NGRP*NCOL + 1)       // 393217
#define N_DTI (NA*NS*NB*MAXLEN)         // 2048000

// ---------------- device scratch (no allocs allowed) ----------------
__device__ float g_S[(size_t)NROW * NCOL];     // 78.6 MB, only valid cols written
__device__ float g_Dsim[NGRP * NCOL];
__device__ int   g_Dind[NGRP * NCOL];
__device__ float g_vis_sum[NCOL];
__device__ int   g_vis_cnt[NCOL];
__device__ float g_Sf[NA * NS * NA];
__device__ int   g_colidx[NCOL];
__device__ int   g_nvalid;

// ---------------- helpers ----------------
__device__ __forceinline__ float warpSum(float v) {
#pragma unroll
    for (int o = 16; o > 0; o >>= 1) v += __shfl_down_sync(0xffffffffu, v, o);
    return v;
}
// All threads must call; returns block sum to all threads. sh must have >=32 floats.
__device__ float blockSum(float v, float* sh) {
    __syncthreads();
    int lane = threadIdx.x & 31, w = threadIdx.x >> 5;
    v = warpSum(v);
    if (lane == 0) sh[w] = v;
    __syncthreads();
    int nw = (blockDim.x + 31) >> 5;
    if (w == 0) {
        float r = (lane < nw) ? sh[lane] : 0.f;
        r = warpSum(r);
        if (lane == 0) sh[0] = r;
    }
    __syncthreads();
    return sh[0];
}

__device__ __forceinline__ float u64lo(unsigned long long v) {
    return __uint_as_float((unsigned)(v & 0xffffffffULL));
}
__device__ __forceinline__ float u64hi(unsigned long long v) {
    return __uint_as_float((unsigned)(v >> 32));
}

// ---------------- kernel 0: compact valid column list ----------------
__global__ void setup_kernel(const int* __restrict__ elen) {
    if (threadIdx.x == 0 && blockIdx.x == 0) {
        int n = 0;
        for (int c = 0; c < NCOL; c++) {
            int a = c / NE, e = c - a * NE;
            if (e < elen[a]) g_colidx[n++] = c;
        }
        g_nvalid = n;
    }
}

// ---------------- kernel 1: SGEMM (valid columns only) ----------------
// C[m][col] = sum_k vis[m][k] * word[col][k], written scattered into g_S.
// BM=128, BN=64, BK=16, 256 threads, thread tile 8(m)x4(n) using fma.rn.f32x2.
#define BM 128
#define BN 64
#define BK 16
__global__ void __launch_bounds__(256) gemm_kernel(const float* __restrict__ vis,
                                                   const float* __restrict__ word) {
    int nt = blockIdx.y;
    int nvalid = g_nvalid;
    if (nt * BN >= nvalid) return;
    int ncols = nvalid - nt * BN;
    if (ncols > BN) ncols = BN;
    int m_base = blockIdx.x * BM;

    __shared__ __align__(16) float As[BK][BM];
    __shared__ __align__(16) float Bs[BK][BN];
    __shared__ int cidx[BN];

    int tid = threadIdx.x;
    if (tid < BN) {
        int t = tid < ncols ? tid : (ncols - 1);
        cidx[tid] = g_colidx[nt * BN + t];
    }
    __syncthreads();

    // compute mapping
    int n_t = tid & 15;          // 0..15
    int m_t = tid >> 4;          // 0..15
    int m0 = m_t * 8;
    int n0 = n_t * 4;

    unsigned long long acc[16];
#pragma unroll
    for (int i = 0; i < 16; i++) acc[i] = 0ULL;

    // loader mapping
    int arow0 = tid >> 2;                 // 0..63
    int akk = (tid & 3) * 4;
    int arow1 = arow0 + 64;
    const float* Aptr0 = vis + (size_t)(m_base + arow0) * DD + akk;
    const float* Aptr1 = vis + (size_t)(m_base + arow1) * DD + akk;
    int brow = tid >> 2;                  // 0..63
    int bkk = (tid & 3) * 4;
    const float* Bptr = word + (size_t)cidx[brow] * DD + bkk;

    float4 ra0 = *(const float4*)Aptr0;
    float4 ra1 = *(const float4*)Aptr1;
    float4 rb  = *(const float4*)Bptr;

    for (int kt = 0; kt < DD / BK; kt++) {
        As[akk + 0][arow0] = ra0.x; As[akk + 1][arow0] = ra0.y;
        As[akk + 2][arow0] = ra0.z; As[akk + 3][arow0] = ra0.w;
        As[akk + 0][arow1] = ra1.x; As[akk + 1][arow1] = ra1.y;
        As[akk + 2][arow1] = ra1.z; As[akk + 3][arow1] = ra1.w;
        Bs[bkk + 0][brow] = rb.x; Bs[bkk + 1][brow] = rb.y;
        Bs[bkk + 2][brow] = rb.z; Bs[bkk + 3][brow] = rb.w;
        __syncthreads();

        if (kt < DD / BK - 1) {
            int koff = (kt + 1) * BK;
            ra0 = *(const float4*)(Aptr0 + koff);
            ra1 = *(const float4*)(Aptr1 + koff);
            rb  = *(const float4*)(Bptr + koff);
        }

#pragma unroll
        for (int k = 0; k < BK; k++) {
            ulonglong2 a01 = *reinterpret_cast<const ulonglong2*>(&As[k][m0]);
            ulonglong2 a23 = *reinterpret_cast<const ulonglong2*>(&As[k][m0 + 4]);
            float4 bf = *reinterpret_cast<const float4*>(&Bs[k][n0]);
            unsigned long long pa0 = a01.x, pa1 = a01.y, pa2 = a23.x, pa3 = a23.y;
            unsigned long long pb0, pb1, pb2, pb3;
            asm("mov.b64 %0, {%1, %1};" : "=l"(pb0) : "f"(bf.x));
            asm("mov.b64 %0, {%1, %1};" : "=l"(pb1) : "f"(bf.y));
            asm("mov.b64 %0, {%1, %1};" : "=l"(pb2) : "f"(bf.z));
            asm("mov.b64 %0, {%1, %1};" : "=l"(pb3) : "f"(bf.w));
#define FMA2(ai, pai) \
            asm("fma.rn.f32x2 %0, %1, %2, %0;" : "+l"(acc[(ai)*4+0]) : "l"(pai), "l"(pb0)); \
            asm("fma.rn.f32x2 %0, %1, %2, %0;" : "+l"(acc[(ai)*4+1]) : "l"(pai), "l"(pb1)); \
            asm("fma.rn.f32x2 %0, %1, %2, %0;" : "+l"(acc[(ai)*4+2]) : "l"(pai), "l"(pb2)); \
            asm("fma.rn.f32x2 %0, %1, %2, %0;" : "+l"(acc[(ai)*4+3]) : "l"(pai), "l"(pb3));
            FMA2(0, pa0) FMA2(1, pa1) FMA2(2, pa2) FMA2(3, pa3)
#undef FMA2
        }
        __syncthreads();
    }

    // writeback (scattered by real column index)
#pragma unroll
    for (int j = 0; j < 4; j++) {
        int nn = n0 + j;
        if (nn < ncols) {
            int col = cidx[nn];
#pragma unroll
            for (int i = 0; i < 4; i++) {
                unsigned long long v = acc[i * 4 + j];
                size_t r = (size_t)(m_base + m0 + 2 * i) * NCOL + col;
                g_S[r] = u64lo(v);
                g_S[r + NCOL] = u64hi(v);
            }
        }
    }
}

// ---------------- kernel 2: max/argmax over Nb per (group, col) ----------------
__global__ void maxred_kernel(const int* __restrict__ elen, float* __restrict__ out) {
    int g = blockIdx.x;        // 0..1023  (= a*NS + s)
    int c = threadIdx.x;       // 0..191
    int aw = c / NE, e = c - aw * NE;
    float best = 0.f;
    int bi = 0;
    if (e < elen[aw]) {
        const float* p = g_S + (size_t)g * NB * NCOL + c;
        best = -3.402823466e+38f;
        bi = 0;
        for (int b = 0; b < NB; b++) {
            float v = p[(size_t)b * NCOL];
            if (v > best) { best = v; bi = b; }
        }
    }
    int idx = g * NCOL + c;
    out[OUT_DIND + idx] = (float)bi;
    out[OUT_DSIM + idx] = best;
    g_Dsim[idx] = best;
    g_Dind[idx] = bi;
}

// ---------------- kernel 3: IoU d_ti_n ----------------
__global__ void iou_kernel(const float* __restrict__ boxes,
                           const float* __restrict__ dets,
                           float* __restrict__ out) {
    int idx = blockIdx.x * blockDim.x + threadIdx.x;
    if (idx >= N_DTI) return;
    int m = idx % MAXLEN;
    int rest = idx / MAXLEN;          // (a*NS+s)*NB + b
    int a = rest / (NS * NB);
    const float* A = boxes + (size_t)rest * 4;
    const float* B = dets + (size_t)(a * MAXLEN + m) * 4;
    float ax0 = A[0], ay0 = A[1], ax1 = A[2], ay1 = A[3];
    float bx0 = B[0], by0 = B[1], bx1 = B[2], by1 = B[3];
    float iw = fminf(ax1, bx1) - fmaxf(ax0, bx0);
    float ih = fminf(ay1, by1) - fmaxf(ay0, by0);
    bool pos = (iw > 0.f) && (ih > 0.f);
    float inter = pos ? iw * ih : 0.f;
    float a1 = (ax1 - ax0) * (ay1 - ay0);
    float a2 = (bx1 - bx0) * (by1 - by0);
    float den = a1 + a2 - inter;
    float r = pos ? inter / (den > 0.f ? den : 1.f) : 0.f;
    out[OUT_DTI + idx] = r;
}

// ---------------- kernel 4: vis-loss partials (closed-form gram) ----------------
// Per valid (a,e): sum_{s!=t}(1 - v_s.v_t) = Ns(Ns-1) - (|sum v|^2 - sum |v_s|^2)
__global__ void __launch_bounds__(256) vis_kernel(const float* __restrict__ vis,
                                                  const int* __restrict__ elen) {
    int a = blockIdx.x / NE, e = blockIdx.x % NE;
    int tid = threadIdx.x;
    __shared__ float red[32];
    __shared__ float s_sim[NS];
    __shared__ int s_ind[NS];
    __shared__ float s_mn, s_mx;
    if (e >= elen[a]) {
        if (tid == 0) { g_vis_sum[blockIdx.x] = 0.f; g_vis_cnt[blockIdx.x] = 0; }
        return;
    }
    if (tid < NS) {
        int r = (a * NS + tid) * NCOL + (a * NE + e);
        s_sim[tid] = g_Dsim[r];
        s_ind[tid] = g_Dind[r];
    }
    __syncthreads();
    if (tid == 0) {
        float mn = s_sim[0], mx = s_sim[0];
        for (int s = 1; s < NS; s++) { mn = fminf(mn, s_sim[s]); mx = fmaxf(mx, s_sim[s]); }
        s_mn = mn; s_mx = mx;
    }
    __syncthreads();
    float mn = s_mn, mx = s_mx;
    float a0 = 0.f, a1 = 0.f;   // this thread's two accumulated dims of sum_s v_s
    float ssum = 0.f;           // sum_s |v_s|^2 (same on all threads)
    int d0 = tid * 2;
    for (int s = 0; s < NS; s++) {
        const float* u = vis + (size_t)((a * NS + s) * NB + s_ind[s]) * DD;
        float x0 = u[d0], x1 = u[d0 + 1];
        float ssq = blockSum(x0 * x0 + x1 * x1, red);
        float nrm = sqrtf(ssq);
        float simn = (s_sim[s] - mn) / (mx - mn + EPSF);
        float f = simn / (nrm + EPSF);
        a0 += x0 * f;
        a1 += x1 * f;
        ssum += f * f * ssq;
    }
    float tot = blockSum(a0 * a0 + a1 * a1, red);   // |sum_s v_s|^2
    if (tid == 0) {
        g_vis_sum[blockIdx.x] = (float)(NS * (NS - 1)) - (tot - ssum);
        g_vis_cnt[blockIdx.x] = NS * (NS - 1);
    }
}

// ---------------- kernel 5a: Sf[a][s][a2] ----------------
__global__ void __launch_bounds__(1024) sf_kernel(const int* __restrict__ elen) {
    int a = blockIdx.x;
    int tid = threadIdx.x;
    __shared__ float smn[NCOL], smx[NCOL];
    if (tid < NCOL) {
        float mn = 3.402823466e+38f, mx = -3.402823466e+38f;
        for (int s = 0; s < NS; s++) {
            float v = g_Dsim[(a * NS + s) * NCOL + tid];
            mn = fminf(mn, v); mx = fmaxf(mx, v);
        }
        smn[tid] = mn; smx[tid] = mx;
    }
    __syncthreads();
    int s = tid >> 4, a2 = tid & 15;
    const float* row = g_Dsim + (size_t)(a * NS + s) * NCOL;
    float acc = 0.f;
    for (int e = 0; e < NE; e++) {
        int c = a2 * NE + e;
        float v = row[c];
        acc += v * (v - smn[c]) / (smx[c] - smn[c] + EPSF);
    }
    int dv = elen[a2]; if (dv < 1) dv = 1;
    g_Sf[(a * NS + s) * NA + a2] = acc / (float)dv;
}

// ---------------- kernel 5b: margin loss ----------------
__global__ void __launch_bounds__(1024) loss_kernel(float* __restrict__ out) {
    int tid = threadIdx.x;
    int x = tid >> 6, s = tid & 63;   // (x, s) over (16, 64)
    __shared__ float red[32];
    float sfd_x = g_Sf[(x * NS + s) * NA + x];   // Sf_diag[x][s]
    float t1 = 0.f, t2 = 0.f;
    for (int aa = 0; aa < NA; aa++) {
        float sf_a = g_Sf[(aa * NS + s) * NA + x];   // Sf[aa, s, x]
        t1 += fmaxf(sf_a - sfd_x + DELTA_F, 0.f);
        float sf_x = g_Sf[(x * NS + s) * NA + aa];   // Sf[x, s, aa]
        t2 += fmaxf(sf_x - sfd_x + DELTA_F, 0.f);
    }
    float fs = (t1 + t2) * (1.0f / (float)NA);
    float tot = blockSum(fs, red);
    if (tid == 0) {
        float vs = 0.f;
        long long vc = 0;
        for (int i = 0; i < NCOL; i++) { vs += g_vis_sum[i]; vc += g_vis_cnt[i]; }
        float vis_loss = vs / (float)(vc > 0 ? vc : 1);
        float margin = (tot / (float)(NA * NS) + 1.0f * vis_loss) * 10.0f;
        out[OUT_MARGIN] = margin;
    }
}

// ---------------- launch ----------------
extern "C" void kernel_launch(void* const* d_in, const int* in_sizes, int n_in,
                              void* d_out, int out_size) {
    const float* vis   = (const float*)d_in[0];
    const float* word  = (const float*)d_in[1];
    const float* boxes = (const float*)d_in[2];
    const float* dets  = (const float*)d_in[3];
    const int*   elen  = (const int*)d_in[4];
    float* out = (float*)d_out;

    setup_kernel<<<1, 32>>>(elen);
    gemm_kernel<<<dim3(NROW / BM, (NCOL + BN - 1) / BN), 256>>>(vis, word);
    maxred_kernel<<<NGRP, NCOL>>>(elen, out);
    iou_kernel<<<(N_DTI + 255) / 256, 256>>>(boxes, dets, out);
    vis_kernel<<<NCOL, 256>>>(vis, elen);
    sf_kernel<<<NA, 1024>>>(elen);
    loss_kernel<<<1, 1024>>>(out);
}

// round 15
// speedup vs baseline: 1.1215x; 1.1215x over previous
#include <cuda_runtime.h>
#include <math.h>
#include <stdint.h>

// Problem constants
#define NA 16
#define NS 64
#define NB 100
#define NE 12
#define MAXLEN 20
#define DD 512
#define NCOL (NA*NE)          // 192
#define NGRP (NA*NS)          // 1024
#define NROW (NGRP*NB)        // 102400
#define EPSF 1e-5f
#define DELTA_F 0.2f

// Output layout (float32, concatenated flattened in return order)
#define OUT_DIND 0
#define OUT_DSIM (NGRP*NCOL)            // 196608
#define OUT_MARGIN (2*NGRP*NCOL)        // 393216
#define OUT_DTI (2*NGRP*NCOL + 1)       // 393217
#define N_DTI (NA*NS*NB*MAXLEN)         // 2048000

// ---------------- device scratch (no allocs allowed) ----------------
__device__ float g_S[(size_t)NROW * NCOL];     // 78.6 MB, only valid cols written
__device__ float g_Dsim[NGRP * NCOL];
__device__ int   g_Dind[NGRP * NCOL];
__device__ float g_vis_sum[NCOL];
__device__ int   g_vis_cnt[NCOL];
__device__ float g_Sf[NA * NS * NA];
__device__ int   g_colidx[NCOL];
__device__ int   g_nvalid;

// ---------------- helpers ----------------
__device__ __forceinline__ float warpSum(float v) {
#pragma unroll
    for (int o = 16; o > 0; o >>= 1) v += __shfl_down_sync(0xffffffffu, v, o);
    return v;
}
// All threads must call; returns block sum to all threads. sh must have >=32 floats.
__device__ float blockSum(float v, float* sh) {
    __syncthreads();
    int lane = threadIdx.x & 31, w = threadIdx.x >> 5;
    v = warpSum(v);
    if (lane == 0) sh[w] = v;
    __syncthreads();
    int nw = (blockDim.x + 31) >> 5;
    if (w == 0) {
        float r = (lane < nw) ? sh[lane] : 0.f;
        r = warpSum(r);
        if (lane == 0) sh[0] = r;
    }
    __syncthreads();
    return sh[0];
}

__device__ __forceinline__ float u64lo(unsigned long long v) {
    return __uint_as_float((unsigned)(v & 0xffffffffULL));
}
__device__ __forceinline__ float u64hi(unsigned long long v) {
    return __uint_as_float((unsigned)(v >> 32));
}

// ---------------- kernel 0: compact valid column list ----------------
__global__ void setup_kernel(const int* __restrict__ elen) {
    if (threadIdx.x == 0 && blockIdx.x == 0) {
        int n = 0;
        for (int c = 0; c < NCOL; c++) {
            int a = c / NE, e = c - a * NE;
            if (e < elen[a]) g_colidx[n++] = c;
        }
        g_nvalid = n;
    }
}

// ---------------- kernel 1: SGEMM (valid columns only) ----------------
// C[m][col] = sum_k vis[m][k] * word[col][k], written scattered into g_S.
// BM=128, BN=128, BK=16, 256 threads, thread tile 8x8 via fma.rn.f32x2,
// double-buffered smem, padded stride 132 (LDS conflict-free).
#define BM 128
#define BN 128
#define BK 16
#define LDA 132

__device__ __forceinline__ void stash_tile(float (*A)[LDA], float (*B)[LDA],
                                           int kk, int arow,
                                           float4 ra0, float4 ra1,
                                           float4 rb0, float4 rb1) {
    A[kk + 0][arow] = ra0.x; A[kk + 1][arow] = ra0.y;
    A[kk + 2][arow] = ra0.z; A[kk + 3][arow] = ra0.w;
    A[kk + 0][arow + 64] = ra1.x; A[kk + 1][arow + 64] = ra1.y;
    A[kk + 2][arow + 64] = ra1.z; A[kk + 3][arow + 64] = ra1.w;
    B[kk + 0][arow] = rb0.x; B[kk + 1][arow] = rb0.y;
    B[kk + 2][arow] = rb0.z; B[kk + 3][arow] = rb0.w;
    B[kk + 0][arow + 64] = rb1.x; B[kk + 1][arow + 64] = rb1.y;
    B[kk + 2][arow + 64] = rb1.z; B[kk + 3][arow + 64] = rb1.w;
}

__global__ void __launch_bounds__(256, 2) gemm_kernel(const float* __restrict__ vis,
                                                      const float* __restrict__ word) {
    int nt = blockIdx.y;
    int nvalid = g_nvalid;
    if (nt * BN >= nvalid) return;
    int ncols = nvalid - nt * BN;
    if (ncols > BN) ncols = BN;
    int m_base = blockIdx.x * BM;

    __shared__ __align__(16) float As[2][BK][LDA];
    __shared__ __align__(16) float Bs[2][BK][LDA];
    __shared__ int cidx[BN];

    int tid = threadIdx.x;
    if (tid < BN) {
        int t = tid < ncols ? tid : (ncols - 1);
        cidx[tid] = g_colidx[nt * BN + t];
    }
    __syncthreads();

    // loader mapping: each thread loads 2 float4 of A and 2 float4 of B per kt
    int arow = tid >> 2;                 // 0..63
    int kk = (tid & 3) * 4;
    const float* Ap0 = vis + (size_t)(m_base + arow) * DD + kk;
    const float* Ap1 = Ap0 + (size_t)64 * DD;
    const float* Bp0 = word + (size_t)cidx[arow] * DD + kk;
    const float* Bp1 = word + (size_t)cidx[arow + 64] * DD + kk;

    // compute mapping: 16x16 thread grid, 8(m)x8(n) per thread
    int m0 = (tid >> 4) * 8;
    int n0 = (tid & 15) * 8;

    unsigned long long acc[32];
#pragma unroll
    for (int i = 0; i < 32; i++) acc[i] = 0ULL;

    float4 ra0 = *(const float4*)Ap0;
    float4 ra1 = *(const float4*)Ap1;
    float4 rb0 = *(const float4*)Bp0;
    float4 rb1 = *(const float4*)Bp1;
    stash_tile(As[0], Bs[0], kk, arow, ra0, ra1, rb0, rb1);
    __syncthreads();

    const int NT = DD / BK;   // 32
    for (int kt = 0; kt < NT; kt++) {
        if (kt + 1 < NT) {
            int koff = (kt + 1) * BK;
            ra0 = *(const float4*)(Ap0 + koff);
            ra1 = *(const float4*)(Ap1 + koff);
            rb0 = *(const float4*)(Bp0 + koff);
            rb1 = *(const float4*)(Bp1 + koff);
        }
        int buf = kt & 1;
#pragma unroll
        for (int k = 0; k < BK; k++) {
            ulonglong2 a01 = *reinterpret_cast<const ulonglong2*>(&As[buf][k][m0]);
            ulonglong2 a23 = *reinterpret_cast<const ulonglong2*>(&As[buf][k][m0 + 4]);
            float4 b0 = *reinterpret_cast<const float4*>(&Bs[buf][k][n0]);
            float4 b1 = *reinterpret_cast<const float4*>(&Bs[buf][k][n0 + 4]);
            unsigned long long pa0 = a01.x, pa1 = a01.y, pa2 = a23.x, pa3 = a23.y;
            unsigned long long pb0, pb1, pb2, pb3, pb4, pb5, pb6, pb7;
            asm("mov.b64 %0, {%1, %1};" : "=l"(pb0) : "f"(b0.x));
            asm("mov.b64 %0, {%1, %1};" : "=l"(pb1) : "f"(b0.y));
            asm("mov.b64 %0, {%1, %1};" : "=l"(pb2) : "f"(b0.z));
            asm("mov.b64 %0, {%1, %1};" : "=l"(pb3) : "f"(b0.w));
            asm("mov.b64 %0, {%1, %1};" : "=l"(pb4) : "f"(b1.x));
            asm("mov.b64 %0, {%1, %1};" : "=l"(pb5) : "f"(b1.y));
            asm("mov.b64 %0, {%1, %1};" : "=l"(pb6) : "f"(b1.z));
            asm("mov.b64 %0, {%1, %1};" : "=l"(pb7) : "f"(b1.w));
#define FMA2ROW(ai, pai) \
            asm("fma.rn.f32x2 %0, %1, %2, %0;" : "+l"(acc[(ai)*8+0]) : "l"(pai), "l"(pb0)); \
            asm("fma.rn.f32x2 %0, %1, %2, %0;" : "+l"(acc[(ai)*8+1]) : "l"(pai), "l"(pb1)); \
            asm("fma.rn.f32x2 %0, %1, %2, %0;" : "+l"(acc[(ai)*8+2]) : "l"(pai), "l"(pb2)); \
            asm("fma.rn.f32x2 %0, %1, %2, %0;" : "+l"(acc[(ai)*8+3]) : "l"(pai), "l"(pb3)); \
            asm("fma.rn.f32x2 %0, %1, %2, %0;" : "+l"(acc[(ai)*8+4]) : "l"(pai), "l"(pb4)); \
            asm("fma.rn.f32x2 %0, %1, %2, %0;" : "+l"(acc[(ai)*8+5]) : "l"(pai), "l"(pb5)); \
            asm("fma.rn.f32x2 %0, %1, %2, %0;" : "+l"(acc[(ai)*8+6]) : "l"(pai), "l"(pb6)); \
            asm("fma.rn.f32x2 %0, %1, %2, %0;" : "+l"(acc[(ai)*8+7]) : "l"(pai), "l"(pb7));
            FMA2ROW(0, pa0) FMA2ROW(1, pa1) FMA2ROW(2, pa2) FMA2ROW(3, pa3)
#undef FMA2ROW
        }
        if (kt + 1 < NT) {
            stash_tile(As[buf ^ 1], Bs[buf ^ 1], kk, arow, ra0, ra1, rb0, rb1);
            __syncthreads();
        }
    }

    // writeback (scattered by real column index)
#pragma unroll
    for (int j = 0; j < 8; j++) {
        int nn = n0 + j;
        if (nn < ncols) {
            int col = cidx[nn];
#pragma unroll
            for (int i = 0; i < 4; i++) {
                unsigned long long v = acc[i * 8 + j];
                size_t r = (size_t)(m_base + m0 + 2 * i) * NCOL + col;
                g_S[r] = u64lo(v);
                g_S[r + NCOL] = u64hi(v);
            }
        }
    }
}

// ---------------- kernel 2: max/argmax over Nb per (group, col) ----------------
__global__ void maxred_kernel(const int* __restrict__ elen, float* __restrict__ out) {
    int g = blockIdx.x;        // 0..1023  (= a*NS + s)
    int c = threadIdx.x;       // 0..191
    int aw = c / NE, e = c - aw * NE;
    float best = 0.f;
    int bi = 0;
    if (e < elen[aw]) {
        const float* p = g_S + (size_t)g * NB * NCOL + c;
        best = -3.402823466e+38f;
        bi = 0;
        for (int b = 0; b < NB; b++) {
            float v = p[(size_t)b * NCOL];
            if (v > best) { best = v; bi = b; }
        }
    }
    int idx = g * NCOL + c;
    out[OUT_DIND + idx] = (float)bi;
    out[OUT_DSIM + idx] = best;
    g_Dsim[idx] = best;
    g_Dind[idx] = bi;
}

// ---------------- kernel 3: IoU d_ti_n ----------------
__global__ void iou_kernel(const float* __restrict__ boxes,
                           const float* __restrict__ dets,
                           float* __restrict__ out) {
    int idx = blockIdx.x * blockDim.x + threadIdx.x;
    if (idx >= N_DTI) return;
    int m = idx % MAXLEN;
    int rest = idx / MAXLEN;          // (a*NS+s)*NB + b
    int a = rest / (NS * NB);
    const float* A = boxes + (size_t)rest * 4;
    const float* B = dets + (size_t)(a * MAXLEN + m) * 4;
    float ax0 = A[0], ay0 = A[1], ax1 = A[2], ay1 = A[3];
    float bx0 = B[0], by0 = B[1], bx1 = B[2], by1 = B[3];
    float iw = fminf(ax1, bx1) - fmaxf(ax0, bx0);
    float ih = fminf(ay1, by1) - fmaxf(ay0, by0);
    bool pos = (iw > 0.f) && (ih > 0.f);
    float inter = pos ? iw * ih : 0.f;
    float a1 = (ax1 - ax0) * (ay1 - ay0);
    float a2 = (bx1 - bx0) * (by1 - by0);
    float den = a1 + a2 - inter;
    float r = pos ? inter / (den > 0.f ? den : 1.f) : 0.f;
    out[OUT_DTI + idx] = r;
}

// ---------------- kernel 4: vis-loss partials (closed-form gram) ----------------
// Per valid (a,e): sum_{s!=t}(1 - v_s.v_t) = Ns(Ns-1) - (|sum v|^2 - sum |v_s|^2)
// Phase A: parallel norms (8 warps x 8 rows). Phase B: factors. Phase C: barrier-free
// accumulation of sum_s v_s per dim-pair, single final blockSum.
__global__ void __launch_bounds__(256) vis_kernel(const float* __restrict__ vis,
                                                  const int* __restrict__ elen) {
    int a = blockIdx.x / NE, e = blockIdx.x % NE;
    int tid = threadIdx.x;
    int lane = tid & 31, w = tid >> 5;
    __shared__ float red[32];
    __shared__ float s_sim[NS];
    __shared__ int s_ind[NS];
    __shared__ float s_ssq[NS];
    __shared__ float s_f[NS];
    __shared__ float s_mn, s_mx;
    if (e >= elen[a]) {
        if (tid == 0) { g_vis_sum[blockIdx.x] = 0.f; g_vis_cnt[blockIdx.x] = 0; }
        return;
    }
    if (tid < NS) {
        int r = (a * NS + tid) * NCOL + (a * NE + e);
        s_sim[tid] = g_Dsim[r];
        s_ind[tid] = g_Dind[r];
    }
    __syncthreads();
    // Phase A: squared norms, one warp per row, 8 rows per warp
    for (int s = w; s < NS; s += 8) {
        const float* u = vis + (size_t)((a * NS + s) * NB + s_ind[s]) * DD;
        const float4* u4 = (const float4*)u + lane * 4;
        float ss = 0.f;
#pragma unroll
        for (int q = 0; q < 4; q++) {
            float4 t = u4[q];
            ss += t.x * t.x + t.y * t.y + t.z * t.z + t.w * t.w;
        }
        ss = warpSum(ss);
        if (lane == 0) s_ssq[s] = ss;
    }
    __syncthreads();
    if (tid == 0) {
        float mn = s_sim[0], mx = s_sim[0];
        for (int s = 1; s < NS; s++) { mn = fminf(mn, s_sim[s]); mx = fmaxf(mx, s_sim[s]); }
        s_mn = mn; s_mx = mx;
    }
    __syncthreads();
    if (tid < NS) {
        float nrm = sqrtf(s_ssq[tid]);
        float simn = (s_sim[tid] - s_mn) / (s_mx - s_mn + EPSF);
        s_f[tid] = simn / (nrm + EPSF);
    }
    __syncthreads();
    // Phase C: accumulate sum_s v_s (2 dims/thread), no barriers in loop
    float a0 = 0.f, a1 = 0.f;
    int d0 = tid * 2;
#pragma unroll 4
    for (int s = 0; s < NS; s++) {
        const float* u = vis + (size_t)((a * NS + s) * NB + s_ind[s]) * DD;
        float f = s_f[s];
        a0 += u[d0] * f;
        a1 += u[d0 + 1] * f;
    }
    float tot = blockSum(a0 * a0 + a1 * a1, red);   // |sum_s v_s|^2
    if (tid == 0) {
        float ssum = 0.f;    // sum_s |v_s|^2 (after scaling)
        for (int s = 0; s < NS; s++) ssum += s_f[s] * s_f[s] * s_ssq[s];
        g_vis_sum[blockIdx.x] = (float)(NS * (NS - 1)) - (tot - ssum);
        g_vis_cnt[blockIdx.x] = NS * (NS - 1);
    }
}

// ---------------- kernel 5a: Sf[a][s][a2] ----------------
__global__ void __launch_bounds__(1024) sf_kernel(const int* __restrict__ elen) {
    int a = blockIdx.x;
    int tid = threadIdx.x;
    __shared__ float smn[NCOL], smx[NCOL];
    if (tid < NCOL) {
        float mn = 3.402823466e+38f, mx = -3.402823466e+38f;
        for (int s = 0; s < NS; s++) {
            float v = g_Dsim[(a * NS + s) * NCOL + tid];
            mn = fminf(mn, v); mx = fmaxf(mx, v);
        }
        smn[tid] = mn; smx[tid] = mx;
    }
    __syncthreads();
    int s = tid >> 4, a2 = tid & 15;
    const float* row = g_Dsim + (size_t)(a * NS + s) * NCOL;
    float acc = 0.f;
    for (int e = 0; e < NE; e++) {
        int c = a2 * NE + e;
        float v = row[c];
        acc += v * (v - smn[c]) / (smx[c] - smn[c] + EPSF);
    }
    int dv = elen[a2]; if (dv < 1) dv = 1;
    g_Sf[(a * NS + s) * NA + a2] = acc / (float)dv;
}

// ---------------- kernel 5b: margin loss ----------------
__global__ void __launch_bounds__(1024) loss_kernel(float* __restrict__ out) {
    int tid = threadIdx.x;
    int x = tid >> 6, s = tid & 63;   // (x, s) over (16, 64)
    __shared__ float red[32];
    float sfd_x = g_Sf[(x * NS + s) * NA + x];   // Sf_diag[x][s]
    float t1 = 0.f, t2 = 0.f;
    for (int aa = 0; aa < NA; aa++) {
        float sf_a = g_Sf[(aa * NS + s) * NA + x];   // Sf[aa, s, x]
        t1 += fmaxf(sf_a - sfd_x + DELTA_F, 0.f);
        float sf_x = g_Sf[(x * NS + s) * NA + aa];   // Sf[x, s, aa]
        t2 += fmaxf(sf_x - sfd_x + DELTA_F, 0.f);
    }
    float fs = (t1 + t2) * (1.0f / (float)NA);
    float tot = blockSum(fs, red);
    if (tid == 0) {
        float vs = 0.f;
        long long vc = 0;
        for (int i = 0; i < NCOL; i++) { vs += g_vis_sum[i]; vc += g_vis_cnt[i]; }
        float vis_loss = vs / (float)(vc > 0 ? vc : 1);
        float margin = (tot / (float)(NA * NS) + 1.0f * vis_loss) * 10.0f;
        out[OUT_MARGIN] = margin;
    }
}

// ---------------- launch ----------------
extern "C" void kernel_launch(void* const* d_in, const int* in_sizes, int n_in,
                              void* d_out, int out_size) {
    const float* vis   = (const float*)d_in[0];
    const float* word  = (const float*)d_in[1];
    const float* boxes = (const float*)d_in[2];
    const float* dets  = (const float*)d_in[3];
    const int*   elen  = (const int*)d_in[4];
    float* out = (float*)d_out;

    setup_kernel<<<1, 32>>>(elen);
    gemm_kernel<<<dim3(NROW / BM, (NCOL + BN - 1) / BN), 256>>>(vis, word);
    maxred_kernel<<<NGRP, NCOL>>>(elen, out);
    iou_kernel<<<(N_DTI + 255) / 256, 256>>>(boxes, dets, out);
    vis_kernel<<<NCOL, 256>>>(vis, elen);
    sf_kernel<<<NA, 1024>>>(elen);
    loss_kernel<<<1, 1024>>>(out);
}